// round 14
// baseline (speedup 1.0000x reference)
#include <cuda_runtime.h>
#include <cuda.h>
#include <cuda_bf16.h>
#include <stdint.h>

#define N_NODES_C  100000
#define N_GRAPHS_C 128
#define D_NODE 96
#define D_EDGE 32
#define HID 16
#define BN_EPS 1e-5f

#define TILE 256
#define THREADS 256
#define RSTRIDE 52        // fallback kernel row stride
#define PSTR 20           // p row stride (floats)
#define NT 256
#define NSLOT 32          // bin slots per graph (128B stride)

// ---- folded parameters ----
struct CP {
    float W[D_EDGE][HID];     // folded edge-part of W1, [j][k] (k-pairs contiguous)
    float B[HID];
    float W2[HID];
    float b2;
    float pad[3];
    float WxT[D_NODE][HID];   // folded node-part of W1, TRANSPOSED [j][k]
};
__constant__ CP c_par;
__device__   CP g_par;

__device__ float g_p[N_NODES_C * HID];            // 6.4 MB (L2-resident)
__device__ float g_bins[N_GRAPHS_C * NSLOT];      // zero-init; finisher re-zeroes
__device__ unsigned g_done = 0;                   // completion counter; reset by finisher

typedef unsigned long long u64;

__device__ __forceinline__ u64 add2(u64 x, u64 y) {
    u64 r; asm("add.rn.f32x2 %0,%1,%2;" : "=l"(r) : "l"(x), "l"(y)); return r;
}

// -------- fold BN into weights --------
__global__ void prep_kernel(const float* __restrict__ W1, const float* __restrict__ b1,
                            const float* __restrict__ gamma, const float* __restrict__ beta,
                            const float* __restrict__ rm, const float* __restrict__ rv,
                            const float* __restrict__ W2, const float* __restrict__ b2) {
    __shared__ float a[HID];
    int lt = threadIdx.x;
    int t  = blockIdx.x * blockDim.x + lt;
    int stride = gridDim.x * blockDim.x;
    if (lt < HID) a[lt] = gamma[lt] * rsqrtf(rv[lt] + BN_EPS);
    __syncthreads();
    for (int i = t; i < D_EDGE * HID; i += stride) {
        int j = i / HID, k = i % HID;
        g_par.W[j][k] = a[k] * W1[k * (D_NODE + D_EDGE) + D_NODE + j];
    }
    for (int i = t; i < D_NODE * HID; i += stride) {
        int j = i / HID, k = i % HID;
        g_par.WxT[j][k] = a[k] * W1[k * (D_NODE + D_EDGE) + j];
    }
    if (t < HID) {
        g_par.B[t]  = a[t] * (b1[t] - rm[t]) + beta[t];
        g_par.W2[t] = W2[t];
    }
    if (t == 0) g_par.b2 = b2[0];
}

// ---- inner j-step: 16 MACs on packed pairs, weights via wide constant loads ----
__device__ __forceinline__ void jstep(u64* A, const u64* wrow, float aval) {
    u64 adup;
    asm("mov.b64 %0,{%1,%1};" : "=l"(adup) : "f"(aval));
    ulonglong2 w01 = *(const ulonglong2*)(wrow + 0);
    ulonglong2 w23 = *(const ulonglong2*)(wrow + 2);
    ulonglong2 w45 = *(const ulonglong2*)(wrow + 4);
    ulonglong2 w67 = *(const ulonglong2*)(wrow + 6);
    asm("fma.rn.f32x2 %0,%1,%2,%0;" : "+l"(A[0]) : "l"(w01.x), "l"(adup));
    asm("fma.rn.f32x2 %0,%1,%2,%0;" : "+l"(A[1]) : "l"(w01.y), "l"(adup));
    asm("fma.rn.f32x2 %0,%1,%2,%0;" : "+l"(A[2]) : "l"(w23.x), "l"(adup));
    asm("fma.rn.f32x2 %0,%1,%2,%0;" : "+l"(A[3]) : "l"(w23.y), "l"(adup));
    asm("fma.rn.f32x2 %0,%1,%2,%0;" : "+l"(A[4]) : "l"(w45.x), "l"(adup));
    asm("fma.rn.f32x2 %0,%1,%2,%0;" : "+l"(A[5]) : "l"(w45.y), "l"(adup));
    asm("fma.rn.f32x2 %0,%1,%2,%0;" : "+l"(A[6]) : "l"(w67.x), "l"(adup));
    asm("fma.rn.f32x2 %0,%1,%2,%0;" : "+l"(A[7]) : "l"(w67.y), "l"(adup));
}

// -------- per-node: p[n][k] = WxT[:,k] . x[n], packed pairs --------
__global__ void __launch_bounds__(NT) node_kernel(const float* __restrict__ x, int n_nodes) {
    int n = blockIdx.x * blockDim.x + threadIdx.x;
    if (n >= n_nodes) return;
    u64 A[8];
#pragma unroll
    for (int p = 0; p < 8; p++) A[p] = 0ULL;
    const float4* xr = (const float4*)(x + (size_t)n * D_NODE);
    const u64* cw = (const u64*)&c_par.WxT[0][0];
#pragma unroll
    for (int jj = 0; jj < D_NODE / 4; jj++) {
        float4 v = __ldg(xr + jj);
        float av[4] = {v.x, v.y, v.z, v.w};
#pragma unroll
        for (int i = 0; i < 4; i++)
            jstep(A, cw + (jj*4 + i) * 8, av[i]);
    }
    u64* po = (u64*)(g_p + (size_t)n * HID);
#pragma unroll
    for (int p = 0; p < 8; p += 2)
        *(ulonglong2*)(po + p) = make_ulonglong2(A[p], A[p+1]);
}

// ---- epilogue: acc pairs -> msg -> RED ----
__device__ __forceinline__ void mlp_tail_and_red(u64* A, bool v, int g, int lane) {
    if (v) {
        float m = c_par.b2;
#pragma unroll
        for (int p = 0; p < 8; p++) {
            float lo, hi;
            asm("mov.b64 {%0,%1},%2;" : "=f"(lo), "=f"(hi) : "l"(A[p]));
            m = fmaf(c_par.W2[2*p],   fmaxf(lo, 0.0f), m);
            m = fmaf(c_par.W2[2*p+1], fmaxf(hi, 0.0f), m);
        }
        atomicAdd(&g_bins[g * NSLOT + lane], m);
    }
}

// ================= TMA edge kernel (R10 structure, TILE=256) =================
// floats: attr[8192] p[5120] src[256] mbar[4]
#define SM_ATTR 0
#define SM_P    8192
#define SM_SRC  (SM_P + TILE * PSTR)        // 13312
#define SM_MBAR (SM_SRC + TILE)             // 13568 (8B aligned)
#define EDGE_SMEM_TMA ((SM_MBAR + 4) * 4)

__global__ void __launch_bounds__(THREADS) edge_kernel_tma(
    const __grid_constant__ CUtensorMap tmap,
    const int* __restrict__ ei,
    const int* __restrict__ batch,
    float* __restrict__ out,
    int n_edges, int n_tiles) {
    extern __shared__ __align__(1024) float sm[];
    float* sAttr = sm + SM_ATTR;
    float* sP    = sm + SM_P;
    int*   sSrc  = (int*)(sm + SM_SRC);
    uint32_t mbar;
    {
        uint32_t base;
        asm("{ .reg .u64 u; cvta.to.shared.u64 u, %1; cvt.u32.u64 %0, u; }"
            : "=r"(base) : "l"(sm));
        mbar = base + SM_MBAR * 4;
    }

    const int t    = threadIdx.x;
    const int lane = t & 31;
    const int e0   = blockIdx.x * TILE;
    const int e    = e0 + t;
    const bool v   = e < n_edges;

    int src = 0, g = 0;
    if (v) {
        src = __ldg(ei + e);
        g   = __ldg(batch + __ldg(ei + n_edges + e));
    }
    sSrc[t] = src;
    __syncthreads();

    if (t == 0) {
        asm volatile("mbarrier.init.shared.b64 [%0], %1;" :: "r"(mbar), "r"(1) : "memory");
        asm volatile("fence.proxy.async.shared::cta;" ::: "memory");
        asm volatile("mbarrier.arrive.expect_tx.shared.b64 _, [%0], %1;"
                     :: "r"(mbar), "r"(TILE * D_EDGE * 4) : "memory");
        uint32_t dst;
        asm("{ .reg .u64 u; cvta.to.shared.u64 u, %1; cvt.u32.u64 %0, u; }"
            : "=r"(dst) : "l"(sAttr));
        asm volatile(
            "cp.async.bulk.tensor.2d.shared::cta.global.tile.mbarrier::complete_tx::bytes "
            "[%0], [%1, {%2, %3}], [%4];"
            :: "r"(dst), "l"(&tmap), "r"(0), "r"(e0), "r"(mbar) : "memory");
    }

    // cooperative p gather under the TMA stream
#pragma unroll
    for (int r = 0; r < (TILE * 4) / THREADS; r++) {
        int idx = r * THREADS + t;
        int el  = idx >> 2;
        int q   = idx & 3;
        int s   = sSrc[el];
        float4 pv = __ldg((const float4*)g_p + (size_t)s * 4 + q);
        *(float4*)(sP + el * PSTR + q * 4) = pv;
    }
    __syncthreads();   // sP ready; mbar init visible

    // wait for TMA (parity 0, single use)
    asm volatile(
        "{\n\t.reg .pred P1;\n"
        "W%=:\n\tmbarrier.try_wait.parity.acquire.cta.shared::cta.b64 P1, [%0], %1, 0x989680;\n"
        "\t@P1 bra.uni D%=;\n\tbra.uni W%=;\nD%=:\n\t}"
        :: "r"(mbar), "r"(0) : "memory");

    const float* myP = sP + t * PSTR;
    const float* myA = sAttr + t * D_EDGE;     // swizzled row
    const int swz = (t & 7);
    const u64* cw = (const u64*)&c_par.W[0][0];
    const u64* cb = (const u64*)&c_par.B[0];

    u64 A[8];
#pragma unroll
    for (int q = 0; q < 2; q++) {
        ulonglong2 p0 = *(const ulonglong2*)(myP + q * 8);
        ulonglong2 p1 = *(const ulonglong2*)(myP + q * 8 + 4);
        A[q*4+0] = add2(p0.x, cb[q*4+0]);
        A[q*4+1] = add2(p0.y, cb[q*4+1]);
        A[q*4+2] = add2(p1.x, cb[q*4+2]);
        A[q*4+3] = add2(p1.y, cb[q*4+3]);
    }
#pragma unroll
    for (int c = 0; c < 8; c++) {
        float4 a4 = *(const float4*)(myA + (c ^ swz) * 4);   // de-swizzle
        float av[4] = {a4.x, a4.y, a4.z, a4.w};
#pragma unroll
        for (int jj = 0; jj < 4; jj++)
            jstep(A, cw + (c*4 + jj) * 8, av[jj]);
    }
    mlp_tail_and_red(A, v, g, lane);

    // ---- fused finish (canonical threadFenceReduction pattern) ----
    __shared__ unsigned sTicket;
    __syncthreads();                        // all REDs of this block issued
    if (t == 0) {
        __threadfence();                    // release: block's REDs visible gpu-wide
        sTicket = atomicAdd(&g_done, 1u);
    }
    __syncthreads();
    if (sTicket == (unsigned)(n_tiles - 1)) {
        __threadfence();                    // acquire: all other blocks' REDs visible
        if (t < N_GRAPHS_C) {
            float s = 0.0f;
#pragma unroll
            for (int i = 0; i < NSLOT; i++) {
                s += __ldcg(&g_bins[t * NSLOT + i]);
                __stcg(&g_bins[t * NSLOT + i], 0.0f);
            }
            out[t] = s;
        }
        if (t == 0) g_done = 0;
    }
}

// ================= fallback edge kernel (R9 path) =================
__global__ void __launch_bounds__(THREADS) edge_kernel_fb(
    const float* __restrict__ edge_attr,
    const int* __restrict__ ei,
    const int* __restrict__ batch,
    int n_edges) {
    extern __shared__ float smf[];
    float* sRow = smf;
    int*   sSrc = (int*)(smf + TILE * RSTRIDE);

    const int t    = threadIdx.x;
    const int lane = t & 31;
    const int e0   = blockIdx.x * TILE;
    const int e    = e0 + t;
    const bool v   = e < n_edges;

    int src = 0, g = 0;
    if (v) {
        src = __ldg(ei + e);
        g   = __ldg(batch + __ldg(ei + n_edges + e));
    }
    sSrc[t] = src;
    __syncthreads();
    {
#pragma unroll
        for (int r = 0; r < (TILE * 4) / THREADS; r++) {
            int idx = r * THREADS + t;
            int el  = idx >> 2;
            int q   = idx & 3;
            int s   = sSrc[el];
            float4 pv = __ldg((const float4*)g_p + (size_t)s * 4 + q);
            *(float4*)(sRow + el * RSTRIDE + D_EDGE + q * 4) = pv;
        }
        const float4* ga = (const float4*)edge_attr;
        const long long base  = (long long)e0 * (D_EDGE / 4);
        const long long total = (long long)n_edges * (D_EDGE / 4);
#pragma unroll
        for (int r = 0; r < (TILE * (D_EDGE / 4)) / THREADS; r++) {
            int idx = r * THREADS + t;
            float4 w = make_float4(0.f, 0.f, 0.f, 0.f);
            if (base + idx < total) w = __ldg(ga + base + idx);
            *(float4*)(sRow + (idx >> 3) * RSTRIDE + (idx & 7) * 4) = w;
        }
    }
    __syncthreads();

    const float* myRow = sRow + t * RSTRIDE;
    const u64* cw = (const u64*)&c_par.W[0][0];
    const u64* cb = (const u64*)&c_par.B[0];
    u64 A[8];
#pragma unroll
    for (int q = 0; q < 2; q++) {
        ulonglong2 p0 = *(const ulonglong2*)(myRow + D_EDGE + q * 8);
        ulonglong2 p1 = *(const ulonglong2*)(myRow + D_EDGE + q * 8 + 4);
        A[q*4+0] = add2(p0.x, cb[q*4+0]);
        A[q*4+1] = add2(p0.y, cb[q*4+1]);
        A[q*4+2] = add2(p1.x, cb[q*4+2]);
        A[q*4+3] = add2(p1.y, cb[q*4+3]);
    }
#pragma unroll
    for (int c = 0; c < 8; c++) {
        float4 a4 = *(const float4*)(myRow + c * 4);
        float av[4] = {a4.x, a4.y, a4.z, a4.w};
#pragma unroll
        for (int jj = 0; jj < 4; jj++)
            jstep(A, cw + (c*4 + jj) * 8, av[jj]);
    }
    mlp_tail_and_red(A, v, g, lane);
}

// -------- finish (fallback path only) --------
__global__ void finish_kernel(float* __restrict__ out) {
    int g = blockIdx.x;
    int lane = threadIdx.x;
    float s = g_bins[g * NSLOT + lane];
    g_bins[g * NSLOT + lane] = 0.0f;
#pragma unroll
    for (int m = 16; m >= 1; m >>= 1) s += __shfl_xor_sync(0xffffffffu, s, m);
    if (lane == 0) out[g] = s;
}

#define EDGE_SMEM_FB (TILE * RSTRIDE * 4 + TILE * 4)

typedef CUresult (*EncodeFn)(CUtensorMap*, CUtensorMapDataType, cuuint32_t, void*,
                             const cuuint64_t*, const cuuint64_t*, const cuuint32_t*,
                             const cuuint32_t*, CUtensorMapInterleave, CUtensorMapSwizzle,
                             CUtensorMapL2promotion, CUtensorMapFloatOOBfill);

extern "C" void kernel_launch(void* const* d_in, const int* in_sizes, int n_in,
                              void* d_out, int out_size) {
    const float* x         = (const float*)d_in[0];
    const float* edge_attr = (const float*)d_in[1];
    const int*   ei        = (const int*)d_in[2];
    const int*   batch     = (const int*)d_in[3];
    const float* W1        = (const float*)d_in[4];
    const float* b1        = (const float*)d_in[5];
    const float* gamma     = (const float*)d_in[6];
    const float* beta      = (const float*)d_in[7];
    const float* rm        = (const float*)d_in[8];
    const float* rv        = (const float*)d_in[9];
    const float* W2        = (const float*)d_in[10];
    const float* b2        = (const float*)d_in[11];
    float* out = (float*)d_out;

    const int n_nodes = in_sizes[0] / D_NODE;
    const int n_edges = in_sizes[1] / D_EDGE;
    const int n_tiles = (n_edges + TILE - 1) / TILE;

    cudaFuncSetAttribute(edge_kernel_tma, cudaFuncAttributeMaxDynamicSharedMemorySize, EDGE_SMEM_TMA);
    cudaFuncSetAttribute(edge_kernel_fb,  cudaFuncAttributeMaxDynamicSharedMemorySize, EDGE_SMEM_FB);

    // build tensormap via runtime-resolved driver entry point (no -lcuda)
    bool use_tma = false;
    CUtensorMap tmap;
    {
        void* sym = nullptr;
        cudaDriverEntryPointQueryResult qr;
        if (cudaGetDriverEntryPoint("cuTensorMapEncodeTiled", &sym,
                                    cudaEnableDefault, &qr) == cudaSuccess &&
            qr == cudaDriverEntryPointSuccess && sym) {
            EncodeFn enc = (EncodeFn)sym;
            cuuint64_t dims[2]    = {(cuuint64_t)D_EDGE, (cuuint64_t)n_edges};
            cuuint64_t strides[1] = {(cuuint64_t)D_EDGE * sizeof(float)};
            cuuint32_t box[2]     = {(cuuint32_t)D_EDGE, (cuuint32_t)TILE};
            cuuint32_t estr[2]    = {1, 1};
            CUresult r = enc(&tmap, CU_TENSOR_MAP_DATA_TYPE_FLOAT32, 2,
                             (void*)edge_attr, dims, strides, box, estr,
                             CU_TENSOR_MAP_INTERLEAVE_NONE, CU_TENSOR_MAP_SWIZZLE_128B,
                             CU_TENSOR_MAP_L2_PROMOTION_L2_128B,
                             CU_TENSOR_MAP_FLOAT_OOB_FILL_NONE);
            use_tma = (r == CUDA_SUCCESS);
        }
    }

    void *c_addr = nullptr, *g_addr = nullptr;
    cudaGetSymbolAddress(&c_addr, c_par);
    cudaGetSymbolAddress(&g_addr, g_par);

    prep_kernel<<<8, 256>>>(W1, b1, gamma, beta, rm, rv, W2, b2);
    cudaMemcpyAsync(c_addr, g_addr, sizeof(CP), cudaMemcpyDeviceToDevice, 0);
    node_kernel<<<(n_nodes + NT - 1) / NT, NT>>>(x, n_nodes);
    if (use_tma) {
        edge_kernel_tma<<<n_tiles, THREADS, EDGE_SMEM_TMA>>>(tmap, ei, batch, out, n_edges, n_tiles);
    } else {
        edge_kernel_fb<<<n_tiles, THREADS, EDGE_SMEM_FB>>>(edge_attr, ei, batch, n_edges);
        finish_kernel<<<N_GRAPHS_C, NSLOT>>>(out);
    }
}

// round 15
// speedup vs baseline: 1.0517x; 1.0517x over previous
#include <cuda_runtime.h>
#include <cuda.h>
#include <cuda_bf16.h>
#include <stdint.h>

#define N_NODES_C  100000
#define N_GRAPHS_C 128
#define D_NODE 96
#define D_EDGE 32
#define HID 16
#define BN_EPS 1e-5f

#define TILE 256
#define THREADS 256
#define RSTRIDE 52        // fallback kernel row stride
#define PSTR 20           // p row stride (floats)
#define NT 256
#define NSLOT 32          // bin slots per graph (128B stride)

// ---- folded parameters ----
struct CP {
    float W[D_EDGE][HID];     // folded edge-part of W1, [j][k] (k-pairs contiguous)
    float B[HID];
    float W2[HID];
    float b2;
    float pad[3];
    float WxT[D_NODE][HID];   // folded node-part of W1, TRANSPOSED [j][k]
};
__constant__ CP c_par;
__device__   CP g_par;

__device__ float g_p[N_NODES_C * HID];            // 6.4 MB (L2-resident)
__device__ float g_bins[N_GRAPHS_C * NSLOT];      // zero-init; finisher re-zeroes
__device__ unsigned g_done = 0;                   // completion ticket; reset by finisher

typedef unsigned long long u64;

__device__ __forceinline__ u64 add2(u64 x, u64 y) {
    u64 r; asm("add.rn.f32x2 %0,%1,%2;" : "=l"(r) : "l"(x), "l"(y)); return r;
}

// -------- fold BN into weights --------
__global__ void prep_kernel(const float* __restrict__ W1, const float* __restrict__ b1,
                            const float* __restrict__ gamma, const float* __restrict__ beta,
                            const float* __restrict__ rm, const float* __restrict__ rv,
                            const float* __restrict__ W2, const float* __restrict__ b2) {
    __shared__ float a[HID];
    int lt = threadIdx.x;
    int t  = blockIdx.x * blockDim.x + lt;
    int stride = gridDim.x * blockDim.x;
    if (lt < HID) a[lt] = gamma[lt] * rsqrtf(rv[lt] + BN_EPS);
    __syncthreads();
    for (int i = t; i < D_EDGE * HID; i += stride) {
        int j = i / HID, k = i % HID;
        g_par.W[j][k] = a[k] * W1[k * (D_NODE + D_EDGE) + D_NODE + j];
    }
    for (int i = t; i < D_NODE * HID; i += stride) {
        int j = i / HID, k = i % HID;
        g_par.WxT[j][k] = a[k] * W1[k * (D_NODE + D_EDGE) + j];
    }
    if (t < HID) {
        g_par.B[t]  = a[t] * (b1[t] - rm[t]) + beta[t];
        g_par.W2[t] = W2[t];
    }
    if (t == 0) g_par.b2 = b2[0];
}

// -------- per-node: p[n][k] = WxT[:,k] . x[n], packed pairs --------
__global__ void __launch_bounds__(NT) node_kernel(const float* __restrict__ x, int n_nodes) {
    int n = blockIdx.x * blockDim.x + threadIdx.x;
    if (n >= n_nodes) return;
    u64 A[8];
#pragma unroll
    for (int p = 0; p < 8; p++) A[p] = 0ULL;
    const float4* xr = (const float4*)(x + (size_t)n * D_NODE);
    const u64* cw = (const u64*)&c_par.WxT[0][0];
#pragma unroll
    for (int jj = 0; jj < D_NODE / 4; jj++) {
        float4 v = __ldg(xr + jj);
        float av[4] = {v.x, v.y, v.z, v.w};
#pragma unroll
        for (int i = 0; i < 4; i++) {
            u64 adup;
            asm("mov.b64 %0,{%1,%1};" : "=l"(adup) : "f"(av[i]));
            const u64* wrow = cw + (jj*4 + i) * 8;
#pragma unroll
            for (int p = 0; p < 8; p++)
                asm("fma.rn.f32x2 %0,%1,%2,%0;" : "+l"(A[p]) : "l"(wrow[p]), "l"(adup));
        }
    }
    u64* po = (u64*)(g_p + (size_t)n * HID);
#pragma unroll
    for (int p = 0; p < 8; p += 2)
        *(ulonglong2*)(po + p) = make_ulonglong2(A[p], A[p+1]);
}

// ---- epilogue: acc pairs -> msg -> RED ----
__device__ __forceinline__ void mlp_tail_and_red(u64* A, bool v, int g, int lane) {
    if (v) {
        float m = c_par.b2;
#pragma unroll
        for (int p = 0; p < 8; p++) {
            float lo, hi;
            asm("mov.b64 {%0,%1},%2;" : "=f"(lo), "=f"(hi) : "l"(A[p]));
            m = fmaf(c_par.W2[2*p],   fmaxf(lo, 0.0f), m);
            m = fmaf(c_par.W2[2*p+1], fmaxf(hi, 0.0f), m);
        }
        atomicAdd(&g_bins[g * NSLOT + lane], m);
    }
}

// ================= TMA edge kernel (exact R10 structure + fence-free fused finish) =================
// floats: attr[8192] p[5120] src[256] mbar[4]
#define SM_ATTR 0
#define SM_P    8192
#define SM_SRC  (SM_P + TILE * PSTR)        // 13312
#define SM_MBAR (SM_SRC + TILE)             // 13568 (8B aligned)
#define EDGE_SMEM_TMA ((SM_MBAR + 4) * 4)

__global__ void __launch_bounds__(THREADS) edge_kernel_tma(
    const __grid_constant__ CUtensorMap tmap,
    const int* __restrict__ ei,
    const int* __restrict__ batch,
    float* __restrict__ out,
    int n_edges, int n_tiles) {
    extern __shared__ __align__(1024) float sm[];
    float* sAttr = sm + SM_ATTR;
    float* sP    = sm + SM_P;
    int*   sSrc  = (int*)(sm + SM_SRC);
    uint32_t mbar;
    {
        uint32_t base;
        asm("{ .reg .u64 u; cvta.to.shared.u64 u, %1; cvt.u32.u64 %0, u; }"
            : "=r"(base) : "l"(sm));
        mbar = base + SM_MBAR * 4;
    }

    const int t    = threadIdx.x;
    const int lane = t & 31;
    const int e0   = blockIdx.x * TILE;
    const int e    = e0 + t;
    const bool v   = e < n_edges;

    int src = 0, g = 0;
    if (v) {
        src = __ldg(ei + e);
        g   = __ldg(batch + __ldg(ei + n_edges + e));
    }
    sSrc[t] = src;
    __syncthreads();

    if (t == 0) {
        asm volatile("mbarrier.init.shared.b64 [%0], %1;" :: "r"(mbar), "r"(1) : "memory");
        asm volatile("fence.proxy.async.shared::cta;" ::: "memory");
        asm volatile("mbarrier.arrive.expect_tx.shared.b64 _, [%0], %1;"
                     :: "r"(mbar), "r"(TILE * D_EDGE * 4) : "memory");
        uint32_t dst;
        asm("{ .reg .u64 u; cvta.to.shared.u64 u, %1; cvt.u32.u64 %0, u; }"
            : "=r"(dst) : "l"(sAttr));
        asm volatile(
            "cp.async.bulk.tensor.2d.shared::cta.global.tile.mbarrier::complete_tx::bytes "
            "[%0], [%1, {%2, %3}], [%4];"
            :: "r"(dst), "l"(&tmap), "r"(0), "r"(e0), "r"(mbar) : "memory");
    }

    // cooperative p gather under the TMA stream
#pragma unroll
    for (int r = 0; r < (TILE * 4) / THREADS; r++) {
        int idx = r * THREADS + t;
        int el  = idx >> 2;
        int q   = idx & 3;
        int s   = sSrc[el];
        float4 pv = __ldg((const float4*)g_p + (size_t)s * 4 + q);
        *(float4*)(sP + el * PSTR + q * 4) = pv;
    }
    __syncthreads();   // sP ready; mbar init visible

    // wait for TMA (parity 0, single use)
    asm volatile(
        "{\n\t.reg .pred P1;\n"
        "W%=:\n\tmbarrier.try_wait.parity.acquire.cta.shared::cta.b64 P1, [%0], %1, 0x989680;\n"
        "\t@P1 bra.uni D%=;\n\tbra.uni W%=;\nD%=:\n\t}"
        :: "r"(mbar), "r"(0) : "memory");

    const float* myP = sP + t * PSTR;
    const float* myA = sAttr + t * D_EDGE;     // swizzled row
    const int swz = (t & 7);
    const u64* cw = (const u64*)&c_par.W[0][0];
    const u64* cb = (const u64*)&c_par.B[0];

    u64 A[8];
#pragma unroll
    for (int q = 0; q < 2; q++) {
        ulonglong2 p0 = *(const ulonglong2*)(myP + q * 8);
        ulonglong2 p1 = *(const ulonglong2*)(myP + q * 8 + 4);
        A[q*4+0] = add2(p0.x, cb[q*4+0]);
        A[q*4+1] = add2(p0.y, cb[q*4+1]);
        A[q*4+2] = add2(p1.x, cb[q*4+2]);
        A[q*4+3] = add2(p1.y, cb[q*4+3]);
    }
#pragma unroll
    for (int c = 0; c < 8; c++) {
        float4 a4 = *(const float4*)(myA + (c ^ swz) * 4);   // de-swizzle
        float av[4] = {a4.x, a4.y, a4.z, a4.w};
#pragma unroll
        for (int jj = 0; jj < 4; jj++) {
            u64 adup;
            asm("mov.b64 %0,{%1,%1};" : "=l"(adup) : "f"(av[jj]));
            const u64* wrow = cw + (c*4 + jj) * 8;           // uniform address, 64-bit LDCU
#pragma unroll
            for (int p = 0; p < 8; p++)
                asm("fma.rn.f32x2 %0,%1,%2,%0;" : "+l"(A[p]) : "l"(wrow[p]), "l"(adup));
        }
    }
    mlp_tail_and_red(A, v, g, lane);

    // ---- fused finish, fence-free: acq_rel ticket atomic carries the ordering ----
    __shared__ unsigned sTicket;
    __syncthreads();                        // block's REDs happen-before t0's release below
    if (t == 0) {
        unsigned tk;
        asm volatile("atom.add.acq_rel.gpu.u32 %0, [%1], 1;"
                     : "=r"(tk) : "l"(&g_done) : "memory");
        sTicket = tk;
    }
    __syncthreads();                        // t0's acquire happens-before all reads below
    if (sTicket == (unsigned)(n_tiles - 1)) {
        if (t < N_GRAPHS_C) {
            float s = 0.0f;
#pragma unroll
            for (int i = 0; i < NSLOT; i++) {
                s += __ldcg(&g_bins[t * NSLOT + i]);
                __stcg(&g_bins[t * NSLOT + i], 0.0f);
            }
            out[t] = s;
        }
        if (t == 0) g_done = 0;             // reset for next graph replay
    }
}

// ================= fallback edge kernel (R9 path) =================
__global__ void __launch_bounds__(THREADS) edge_kernel_fb(
    const float* __restrict__ edge_attr,
    const int* __restrict__ ei,
    const int* __restrict__ batch,
    int n_edges) {
    extern __shared__ float smf[];
    float* sRow = smf;
    int*   sSrc = (int*)(smf + TILE * RSTRIDE);

    const int t    = threadIdx.x;
    const int lane = t & 31;
    const int e0   = blockIdx.x * TILE;
    const int e    = e0 + t;
    const bool v   = e < n_edges;

    int src = 0, g = 0;
    if (v) {
        src = __ldg(ei + e);
        g   = __ldg(batch + __ldg(ei + n_edges + e));
    }
    sSrc[t] = src;
    __syncthreads();
    {
#pragma unroll
        for (int r = 0; r < (TILE * 4) / THREADS; r++) {
            int idx = r * THREADS + t;
            int el  = idx >> 2;
            int q   = idx & 3;
            int s   = sSrc[el];
            float4 pv = __ldg((const float4*)g_p + (size_t)s * 4 + q);
            *(float4*)(sRow + el * RSTRIDE + D_EDGE + q * 4) = pv;
        }
        const float4* ga = (const float4*)edge_attr;
        const long long base  = (long long)e0 * (D_EDGE / 4);
        const long long total = (long long)n_edges * (D_EDGE / 4);
#pragma unroll
        for (int r = 0; r < (TILE * (D_EDGE / 4)) / THREADS; r++) {
            int idx = r * THREADS + t;
            float4 w = make_float4(0.f, 0.f, 0.f, 0.f);
            if (base + idx < total) w = __ldg(ga + base + idx);
            *(float4*)(sRow + (idx >> 3) * RSTRIDE + (idx & 7) * 4) = w;
        }
    }
    __syncthreads();

    const float* myRow = sRow + t * RSTRIDE;
    const u64* cw = (const u64*)&c_par.W[0][0];
    const u64* cb = (const u64*)&c_par.B[0];
    u64 A[8];
#pragma unroll
    for (int q = 0; q < 2; q++) {
        ulonglong2 p0 = *(const ulonglong2*)(myRow + D_EDGE + q * 8);
        ulonglong2 p1 = *(const ulonglong2*)(myRow + D_EDGE + q * 8 + 4);
        A[q*4+0] = add2(p0.x, cb[q*4+0]);
        A[q*4+1] = add2(p0.y, cb[q*4+1]);
        A[q*4+2] = add2(p1.x, cb[q*4+2]);
        A[q*4+3] = add2(p1.y, cb[q*4+3]);
    }
#pragma unroll
    for (int c = 0; c < 8; c++) {
        float4 a4 = *(const float4*)(myRow + c * 4);
        float av[4] = {a4.x, a4.y, a4.z, a4.w};
#pragma unroll
        for (int jj = 0; jj < 4; jj++) {
            u64 adup;
            asm("mov.b64 %0,{%1,%1};" : "=l"(adup) : "f"(av[jj]));
            const u64* wrow = cw + (c*4 + jj) * 8;
#pragma unroll
            for (int p = 0; p < 8; p++)
                asm("fma.rn.f32x2 %0,%1,%2,%0;" : "+l"(A[p]) : "l"(wrow[p]), "l"(adup));
        }
    }
    mlp_tail_and_red(A, v, g, lane);
}

// -------- finish (fallback path only) --------
__global__ void finish_kernel(float* __restrict__ out) {
    int g = blockIdx.x;
    int lane = threadIdx.x;
    float s = g_bins[g * NSLOT + lane];
    g_bins[g * NSLOT + lane] = 0.0f;
#pragma unroll
    for (int m = 16; m >= 1; m >>= 1) s += __shfl_xor_sync(0xffffffffu, s, m);
    if (lane == 0) out[g] = s;
}

#define EDGE_SMEM_FB (TILE * RSTRIDE * 4 + TILE * 4)

typedef CUresult (*EncodeFn)(CUtensorMap*, CUtensorMapDataType, cuuint32_t, void*,
                             const cuuint64_t*, const cuuint64_t*, const cuuint32_t*,
                             const cuuint32_t*, CUtensorMapInterleave, CUtensorMapSwizzle,
                             CUtensorMapL2promotion, CUtensorMapFloatOOBfill);

extern "C" void kernel_launch(void* const* d_in, const int* in_sizes, int n_in,
                              void* d_out, int out_size) {
    const float* x         = (const float*)d_in[0];
    const float* edge_attr = (const float*)d_in[1];
    const int*   ei        = (const int*)d_in[2];
    const int*   batch     = (const int*)d_in[3];
    const float* W1        = (const float*)d_in[4];
    const float* b1        = (const float*)d_in[5];
    const float* gamma     = (const float*)d_in[6];
    const float* beta      = (const float*)d_in[7];
    const float* rm        = (const float*)d_in[8];
    const float* rv        = (const float*)d_in[9];
    const float* W2        = (const float*)d_in[10];
    const float* b2        = (const float*)d_in[11];
    float* out = (float*)d_out;

    const int n_nodes = in_sizes[0] / D_NODE;
    const int n_edges = in_sizes[1] / D_EDGE;
    const int n_tiles = (n_edges + TILE - 1) / TILE;

    cudaFuncSetAttribute(edge_kernel_tma, cudaFuncAttributeMaxDynamicSharedMemorySize, EDGE_SMEM_TMA);
    cudaFuncSetAttribute(edge_kernel_fb,  cudaFuncAttributeMaxDynamicSharedMemorySize, EDGE_SMEM_FB);

    // build tensormap via runtime-resolved driver entry point (no -lcuda)
    bool use_tma = false;
    CUtensorMap tmap;
    {
        void* sym = nullptr;
        cudaDriverEntryPointQueryResult qr;
        if (cudaGetDriverEntryPoint("cuTensorMapEncodeTiled", &sym,
                                    cudaEnableDefault, &qr) == cudaSuccess &&
            qr == cudaDriverEntryPointSuccess && sym) {
            EncodeFn enc = (EncodeFn)sym;
            cuuint64_t dims[2]    = {(cuuint64_t)D_EDGE, (cuuint64_t)n_edges};
            cuuint64_t strides[1] = {(cuuint64_t)D_EDGE * sizeof(float)};
            cuuint32_t box[2]     = {(cuuint32_t)D_EDGE, (cuuint32_t)TILE};
            cuuint32_t estr[2]    = {1, 1};
            CUresult r = enc(&tmap, CU_TENSOR_MAP_DATA_TYPE_FLOAT32, 2,
                             (void*)edge_attr, dims, strides, box, estr,
                             CU_TENSOR_MAP_INTERLEAVE_NONE, CU_TENSOR_MAP_SWIZZLE_128B,
                             CU_TENSOR_MAP_L2_PROMOTION_L2_128B,
                             CU_TENSOR_MAP_FLOAT_OOB_FILL_NONE);
            use_tma = (r == CUDA_SUCCESS);
        }
    }

    void *c_addr = nullptr, *g_addr = nullptr;
    cudaGetSymbolAddress(&c_addr, c_par);
    cudaGetSymbolAddress(&g_addr, g_par);

    prep_kernel<<<8, 256>>>(W1, b1, gamma, beta, rm, rv, W2, b2);
    cudaMemcpyAsync(c_addr, g_addr, sizeof(CP), cudaMemcpyDeviceToDevice, 0);
    node_kernel<<<(n_nodes + NT - 1) / NT, NT>>>(x, n_nodes);
    if (use_tma) {
        edge_kernel_tma<<<n_tiles, THREADS, EDGE_SMEM_TMA>>>(tmap, ei, batch, out, n_edges, n_tiles);
    } else {
        edge_kernel_fb<<<n_tiles, THREADS, EDGE_SMEM_FB>>>(edge_attr, ei, batch, n_edges);
        finish_kernel<<<N_GRAPHS_C, NSLOT>>>(out);
    }
}

// round 16
// speedup vs baseline: 1.1623x; 1.1052x over previous
#include <cuda_runtime.h>
#include <cuda.h>
#include <cuda_bf16.h>
#include <stdint.h>

#define N_NODES_C  100000
#define N_GRAPHS_C 128
#define D_NODE 96
#define D_EDGE 32
#define HID 16
#define BN_EPS 1e-5f

#define TILE 256
#define THREADS 256
#define RSTRIDE 52        // fallback kernel row stride
#define PSTR 20           // p row stride (floats)
#define NT 256
#define NSLOT 32          // bin slots per graph (128B stride)

// ---- folded parameters ----
struct CP {
    float W[D_EDGE][HID];     // folded edge-part of W1, [j][k] (k-pairs contiguous)
    float B[HID];
    float W2[HID];
    float b2;
    float pad[3];
    float WxT[D_NODE][HID];   // folded node-part of W1, TRANSPOSED [j][k]
};
__constant__ CP c_par;
__device__   CP g_par;

__device__ float g_p[N_NODES_C * HID];            // 6.4 MB (L2-resident)
__device__ float g_bins[N_GRAPHS_C * NSLOT];      // zero-init; finish re-zeroes

typedef unsigned long long u64;

__device__ __forceinline__ u64 add2(u64 x, u64 y) {
    u64 r; asm("add.rn.f32x2 %0,%1,%2;" : "=l"(r) : "l"(x), "l"(y)); return r;
}

// -------- fold BN into weights --------
__global__ void prep_kernel(const float* __restrict__ W1, const float* __restrict__ b1,
                            const float* __restrict__ gamma, const float* __restrict__ beta,
                            const float* __restrict__ rm, const float* __restrict__ rv,
                            const float* __restrict__ W2, const float* __restrict__ b2) {
    __shared__ float a[HID];
    int lt = threadIdx.x;
    int t  = blockIdx.x * blockDim.x + lt;
    int stride = gridDim.x * blockDim.x;
    if (lt < HID) a[lt] = gamma[lt] * rsqrtf(rv[lt] + BN_EPS);
    __syncthreads();
    for (int i = t; i < D_EDGE * HID; i += stride) {
        int j = i / HID, k = i % HID;
        g_par.W[j][k] = a[k] * W1[k * (D_NODE + D_EDGE) + D_NODE + j];
    }
    for (int i = t; i < D_NODE * HID; i += stride) {
        int j = i / HID, k = i % HID;
        g_par.WxT[j][k] = a[k] * W1[k * (D_NODE + D_EDGE) + j];
    }
    if (t < HID) {
        g_par.B[t]  = a[t] * (b1[t] - rm[t]) + beta[t];
        g_par.W2[t] = W2[t];
    }
    if (t == 0) g_par.b2 = b2[0];
}

// -------- per-node: p[n][k] = WxT[:,k] . x[n], packed pairs --------
__global__ void __launch_bounds__(NT) node_kernel(const float* __restrict__ x, int n_nodes) {
    int n = blockIdx.x * blockDim.x + threadIdx.x;
    if (n >= n_nodes) return;
    u64 A[8];
#pragma unroll
    for (int p = 0; p < 8; p++) A[p] = 0ULL;
    const float4* xr = (const float4*)(x + (size_t)n * D_NODE);
    const u64* cw = (const u64*)&c_par.WxT[0][0];
#pragma unroll
    for (int jj = 0; jj < D_NODE / 4; jj++) {
        float4 v = __ldg(xr + jj);
        float av[4] = {v.x, v.y, v.z, v.w};
#pragma unroll
        for (int i = 0; i < 4; i++) {
            u64 adup;
            asm("mov.b64 %0,{%1,%1};" : "=l"(adup) : "f"(av[i]));
            const u64* wrow = cw + (jj*4 + i) * 8;
#pragma unroll
            for (int p = 0; p < 8; p++)
                asm("fma.rn.f32x2 %0,%1,%2,%0;" : "+l"(A[p]) : "l"(wrow[p]), "l"(adup));
        }
    }
    u64* po = (u64*)(g_p + (size_t)n * HID);
#pragma unroll
    for (int p = 0; p < 8; p += 2)
        *(ulonglong2*)(po + p) = make_ulonglong2(A[p], A[p+1]);
}

// ---- epilogue: acc pairs -> msg -> RED ----
__device__ __forceinline__ void mlp_tail_and_red(u64* A, bool v, int g, int lane) {
    if (v) {
        float m = c_par.b2;
#pragma unroll
        for (int p = 0; p < 8; p++) {
            float lo, hi;
            asm("mov.b64 {%0,%1},%2;" : "=f"(lo), "=f"(hi) : "l"(A[p]));
            m = fmaf(c_par.W2[2*p],   fmaxf(lo, 0.0f), m);
            m = fmaf(c_par.W2[2*p+1], fmaxf(hi, 0.0f), m);
        }
        atomicAdd(&g_bins[g * NSLOT + lane], m);
    }
}

// ================= TMA edge kernel (R10 minus the sSrc round-trip) =================
// floats: attr[8192] p[5120] mbar[4]
#define SM_ATTR 0
#define SM_P    8192
#define SM_MBAR (SM_P + TILE * PSTR)        // 13312 (8B aligned: *4 = 53248)
#define EDGE_SMEM_TMA ((SM_MBAR + 4) * 4)

__global__ void __launch_bounds__(THREADS) edge_kernel_tma(
    const __grid_constant__ CUtensorMap tmap,
    const int* __restrict__ ei,
    const int* __restrict__ batch,
    int n_edges) {
    extern __shared__ __align__(1024) float sm[];
    float* sAttr = sm + SM_ATTR;
    float* sP    = sm + SM_P;
    uint32_t mbar;
    {
        uint32_t base;
        asm("{ .reg .u64 u; cvta.to.shared.u64 u, %1; cvt.u32.u64 %0, u; }"
            : "=r"(base) : "l"(sm));
        mbar = base + SM_MBAR * 4;
    }

    const int t    = threadIdx.x;
    const int lane = t & 31;
    const int e0   = blockIdx.x * TILE;
    const int e    = e0 + t;
    const bool v   = e < n_edges;

    // t0 issues the TMA immediately — nothing gates it
    if (t == 0) {
        asm volatile("mbarrier.init.shared.b64 [%0], %1;" :: "r"(mbar), "r"(1) : "memory");
        asm volatile("fence.proxy.async.shared::cta;" ::: "memory");
        asm volatile("mbarrier.arrive.expect_tx.shared.b64 _, [%0], %1;"
                     :: "r"(mbar), "r"(TILE * D_EDGE * 4) : "memory");
        uint32_t dst;
        asm("{ .reg .u64 u; cvta.to.shared.u64 u, %1; cvt.u32.u64 %0, u; }"
            : "=r"(dst) : "l"(sAttr));
        asm volatile(
            "cp.async.bulk.tensor.2d.shared::cta.global.tile.mbarrier::complete_tx::bytes "
            "[%0], [%1, {%2, %3}], [%4];"
            :: "r"(dst), "l"(&tmap), "r"(0), "r"(e0), "r"(mbar) : "memory");
    }

    // epilogue bin index (independent of staging)
    int g = 0;
    if (v) g = __ldg(batch + __ldg(ei + n_edges + e));

    // cooperative p gather under the TMA stream; src re-read directly from ei
    // (4 lanes per edge share one ei word -> 8 addrs/warp in 32B = 1 sector)
#pragma unroll
    for (int r = 0; r < (TILE * 4) / THREADS; r++) {
        int idx = r * THREADS + t;
        int el  = idx >> 2;
        int q   = idx & 3;
        int ee  = e0 + el;
        int s   = (ee < n_edges) ? __ldg(ei + ee) : 0;
        float4 pv = __ldg((const float4*)g_p + (size_t)s * 4 + q);
        *(float4*)(sP + el * PSTR + q * 4) = pv;
    }
    __syncthreads();   // sP visible; mbar init visible to all waiters

    // wait for TMA (parity 0, single use)
    asm volatile(
        "{\n\t.reg .pred P1;\n"
        "W%=:\n\tmbarrier.try_wait.parity.acquire.cta.shared::cta.b64 P1, [%0], %1, 0x989680;\n"
        "\t@P1 bra.uni D%=;\n\tbra.uni W%=;\nD%=:\n\t}"
        :: "r"(mbar), "r"(0) : "memory");

    const float* myP = sP + t * PSTR;
    const float* myA = sAttr + t * D_EDGE;     // swizzled row
    const int swz = (t & 7);
    const u64* cw = (const u64*)&c_par.W[0][0];
    const u64* cb = (const u64*)&c_par.B[0];

    u64 A[8];
#pragma unroll
    for (int q = 0; q < 2; q++) {
        ulonglong2 p0 = *(const ulonglong2*)(myP + q * 8);
        ulonglong2 p1 = *(const ulonglong2*)(myP + q * 8 + 4);
        A[q*4+0] = add2(p0.x, cb[q*4+0]);
        A[q*4+1] = add2(p0.y, cb[q*4+1]);
        A[q*4+2] = add2(p1.x, cb[q*4+2]);
        A[q*4+3] = add2(p1.y, cb[q*4+3]);
    }
#pragma unroll
    for (int c = 0; c < 8; c++) {
        float4 a4 = *(const float4*)(myA + (c ^ swz) * 4);   // de-swizzle
        float av[4] = {a4.x, a4.y, a4.z, a4.w};
#pragma unroll
        for (int jj = 0; jj < 4; jj++) {
            u64 adup;
            asm("mov.b64 %0,{%1,%1};" : "=l"(adup) : "f"(av[jj]));
            const u64* wrow = cw + (c*4 + jj) * 8;           // uniform address, 64-bit LDCU
#pragma unroll
            for (int p = 0; p < 8; p++)
                asm("fma.rn.f32x2 %0,%1,%2,%0;" : "+l"(A[p]) : "l"(wrow[p]), "l"(adup));
        }
    }
    mlp_tail_and_red(A, v, g, lane);
}

// ================= fallback edge kernel (R9 path) =================
__global__ void __launch_bounds__(THREADS) edge_kernel_fb(
    const float* __restrict__ edge_attr,
    const int* __restrict__ ei,
    const int* __restrict__ batch,
    int n_edges) {
    extern __shared__ float smf[];
    float* sRow = smf;
    int*   sSrc = (int*)(smf + TILE * RSTRIDE);

    const int t    = threadIdx.x;
    const int lane = t & 31;
    const int e0   = blockIdx.x * TILE;
    const int e    = e0 + t;
    const bool v   = e < n_edges;

    int src = 0, g = 0;
    if (v) {
        src = __ldg(ei + e);
        g   = __ldg(batch + __ldg(ei + n_edges + e));
    }
    sSrc[t] = src;
    __syncthreads();
    {
#pragma unroll
        for (int r = 0; r < (TILE * 4) / THREADS; r++) {
            int idx = r * THREADS + t;
            int el  = idx >> 2;
            int q   = idx & 3;
            int s   = sSrc[el];
            float4 pv = __ldg((const float4*)g_p + (size_t)s * 4 + q);
            *(float4*)(sRow + el * RSTRIDE + D_EDGE + q * 4) = pv;
        }
        const float4* ga = (const float4*)edge_attr;
        const long long base  = (long long)e0 * (D_EDGE / 4);
        const long long total = (long long)n_edges * (D_EDGE / 4);
#pragma unroll
        for (int r = 0; r < (TILE * (D_EDGE / 4)) / THREADS; r++) {
            int idx = r * THREADS + t;
            float4 w = make_float4(0.f, 0.f, 0.f, 0.f);
            if (base + idx < total) w = __ldg(ga + base + idx);
            *(float4*)(sRow + (idx >> 3) * RSTRIDE + (idx & 7) * 4) = w;
        }
    }
    __syncthreads();

    const float* myRow = sRow + t * RSTRIDE;
    const u64* cw = (const u64*)&c_par.W[0][0];
    const u64* cb = (const u64*)&c_par.B[0];
    u64 A[8];
#pragma unroll
    for (int q = 0; q < 2; q++) {
        ulonglong2 p0 = *(const ulonglong2*)(myRow + D_EDGE + q * 8);
        ulonglong2 p1 = *(const ulonglong2*)(myRow + D_EDGE + q * 8 + 4);
        A[q*4+0] = add2(p0.x, cb[q*4+0]);
        A[q*4+1] = add2(p0.y, cb[q*4+1]);
        A[q*4+2] = add2(p1.x, cb[q*4+2]);
        A[q*4+3] = add2(p1.y, cb[q*4+3]);
    }
#pragma unroll
    for (int c = 0; c < 8; c++) {
        float4 a4 = *(const float4*)(myRow + c * 4);
        float av[4] = {a4.x, a4.y, a4.z, a4.w};
#pragma unroll
        for (int jj = 0; jj < 4; jj++) {
            u64 adup;
            asm("mov.b64 %0,{%1,%1};" : "=l"(adup) : "f"(av[jj]));
            const u64* wrow = cw + (c*4 + jj) * 8;
#pragma unroll
            for (int p = 0; p < 8; p++)
                asm("fma.rn.f32x2 %0,%1,%2,%0;" : "+l"(A[p]) : "l"(wrow[p]), "l"(adup));
        }
    }
    mlp_tail_and_red(A, v, g, lane);
}

// -------- finish: one block per graph, warp reduce, write + re-zero --------
__global__ void finish_kernel(float* __restrict__ out) {
    int g = blockIdx.x;
    int lane = threadIdx.x;
    float s = g_bins[g * NSLOT + lane];
    g_bins[g * NSLOT + lane] = 0.0f;
#pragma unroll
    for (int m = 16; m >= 1; m >>= 1) s += __shfl_xor_sync(0xffffffffu, s, m);
    if (lane == 0) out[g] = s;
}

#define EDGE_SMEM_FB (TILE * RSTRIDE * 4 + TILE * 4)

typedef CUresult (*EncodeFn)(CUtensorMap*, CUtensorMapDataType, cuuint32_t, void*,
                             const cuuint64_t*, const cuuint64_t*, const cuuint32_t*,
                             const cuuint32_t*, CUtensorMapInterleave, CUtensorMapSwizzle,
                             CUtensorMapL2promotion, CUtensorMapFloatOOBfill);

extern "C" void kernel_launch(void* const* d_in, const int* in_sizes, int n_in,
                              void* d_out, int out_size) {
    const float* x         = (const float*)d_in[0];
    const float* edge_attr = (const float*)d_in[1];
    const int*   ei        = (const int*)d_in[2];
    const int*   batch     = (const int*)d_in[3];
    const float* W1        = (const float*)d_in[4];
    const float* b1        = (const float*)d_in[5];
    const float* gamma     = (const float*)d_in[6];
    const float* beta      = (const float*)d_in[7];
    const float* rm        = (const float*)d_in[8];
    const float* rv        = (const float*)d_in[9];
    const float* W2        = (const float*)d_in[10];
    const float* b2        = (const float*)d_in[11];
    float* out = (float*)d_out;

    const int n_nodes = in_sizes[0] / D_NODE;
    const int n_edges = in_sizes[1] / D_EDGE;
    const int n_tiles = (n_edges + TILE - 1) / TILE;

    cudaFuncSetAttribute(edge_kernel_tma, cudaFuncAttributeMaxDynamicSharedMemorySize, EDGE_SMEM_TMA);
    cudaFuncSetAttribute(edge_kernel_fb,  cudaFuncAttributeMaxDynamicSharedMemorySize, EDGE_SMEM_FB);

    // build tensormap via runtime-resolved driver entry point (no -lcuda)
    bool use_tma = false;
    CUtensorMap tmap;
    {
        void* sym = nullptr;
        cudaDriverEntryPointQueryResult qr;
        if (cudaGetDriverEntryPoint("cuTensorMapEncodeTiled", &sym,
                                    cudaEnableDefault, &qr) == cudaSuccess &&
            qr == cudaDriverEntryPointSuccess && sym) {
            EncodeFn enc = (EncodeFn)sym;
            cuuint64_t dims[2]    = {(cuuint64_t)D_EDGE, (cuuint64_t)n_edges};
            cuuint64_t strides[1] = {(cuuint64_t)D_EDGE * sizeof(float)};
            cuuint32_t box[2]     = {(cuuint32_t)D_EDGE, (cuuint32_t)TILE};
            cuuint32_t estr[2]    = {1, 1};
            CUresult r = enc(&tmap, CU_TENSOR_MAP_DATA_TYPE_FLOAT32, 2,
                             (void*)edge_attr, dims, strides, box, estr,
                             CU_TENSOR_MAP_INTERLEAVE_NONE, CU_TENSOR_MAP_SWIZZLE_128B,
                             CU_TENSOR_MAP_L2_PROMOTION_L2_128B,
                             CU_TENSOR_MAP_FLOAT_OOB_FILL_NONE);
            use_tma = (r == CUDA_SUCCESS);
        }
    }

    void *c_addr = nullptr, *g_addr = nullptr;
    cudaGetSymbolAddress(&c_addr, c_par);
    cudaGetSymbolAddress(&g_addr, g_par);

    prep_kernel<<<8, 256>>>(W1, b1, gamma, beta, rm, rv, W2, b2);
    cudaMemcpyAsync(c_addr, g_addr, sizeof(CP), cudaMemcpyDeviceToDevice, 0);
    node_kernel<<<(n_nodes + NT - 1) / NT, NT>>>(x, n_nodes);
    if (use_tma)
        edge_kernel_tma<<<n_tiles, THREADS, EDGE_SMEM_TMA>>>(tmap, ei, batch, n_edges);
    else
        edge_kernel_fb<<<n_tiles, THREADS, EDGE_SMEM_FB>>>(edge_attr, ei, batch, n_edges);
    finish_kernel<<<N_GRAPHS_C, NSLOT>>>(out);
}

// round 17
// speedup vs baseline: 1.1678x; 1.0047x over previous
#include <cuda_runtime.h>
#include <cuda.h>
#include <cuda_bf16.h>
#include <stdint.h>

#define N_NODES_C  100000
#define N_GRAPHS_C 128
#define D_NODE 96
#define D_EDGE 32
#define HID 16
#define BN_EPS 1e-5f

#define TILE 256
#define THREADS 256
#define RSTRIDE 52        // fallback kernel row stride
#define PSTR 20           // p row stride (floats)
#define NT 256
#define NSLOT 32          // bin slots per graph (128B stride)

// ---- folded parameters ----
struct CP {
    float W[D_EDGE][HID];     // folded edge-part of W1, [j][k] (k-pairs contiguous)
    float B[HID];
    float W2[HID];
    float b2;
    float pad[3];
    float WxT[D_NODE][HID];   // folded node-part of W1, TRANSPOSED [j][k]
};
__constant__ CP c_par;
__device__   CP g_par;

__device__ float g_p[N_NODES_C * HID];            // 6.4 MB (L2-resident)
__device__ float g_bins[N_GRAPHS_C * NSLOT];      // zero-init; finish re-zeroes

typedef unsigned long long u64;

__device__ __forceinline__ u64 add2(u64 x, u64 y) {
    u64 r; asm("add.rn.f32x2 %0,%1,%2;" : "=l"(r) : "l"(x), "l"(y)); return r;
}

// -------- fold BN into weights --------
__global__ void prep_kernel(const float* __restrict__ W1, const float* __restrict__ b1,
                            const float* __restrict__ gamma, const float* __restrict__ beta,
                            const float* __restrict__ rm, const float* __restrict__ rv,
                            const float* __restrict__ W2, const float* __restrict__ b2) {
    __shared__ float a[HID];
    int lt = threadIdx.x;
    int t  = blockIdx.x * blockDim.x + lt;
    int stride = gridDim.x * blockDim.x;
    if (lt < HID) a[lt] = gamma[lt] * rsqrtf(rv[lt] + BN_EPS);
    __syncthreads();
    for (int i = t; i < D_EDGE * HID; i += stride) {
        int j = i / HID, k = i % HID;
        g_par.W[j][k] = a[k] * W1[k * (D_NODE + D_EDGE) + D_NODE + j];
    }
    for (int i = t; i < D_NODE * HID; i += stride) {
        int j = i / HID, k = i % HID;
        g_par.WxT[j][k] = a[k] * W1[k * (D_NODE + D_EDGE) + j];
    }
    if (t < HID) {
        g_par.B[t]  = a[t] * (b1[t] - rm[t]) + beta[t];
        g_par.W2[t] = W2[t];
    }
    if (t == 0) g_par.b2 = b2[0];
}

// -------- per-node: p[n][k] = WxT[:,k] . x[n], packed pairs --------
__global__ void __launch_bounds__(NT) node_kernel(const float* __restrict__ x, int n_nodes) {
    int n = blockIdx.x * blockDim.x + threadIdx.x;
    if (n >= n_nodes) return;
    u64 A[8];
#pragma unroll
    for (int p = 0; p < 8; p++) A[p] = 0ULL;
    const float4* xr = (const float4*)(x + (size_t)n * D_NODE);
    const u64* cw = (const u64*)&c_par.WxT[0][0];
#pragma unroll
    for (int jj = 0; jj < D_NODE / 4; jj++) {
        float4 v = __ldg(xr + jj);
        float av[4] = {v.x, v.y, v.z, v.w};
#pragma unroll
        for (int i = 0; i < 4; i++) {
            u64 adup;
            asm("mov.b64 %0,{%1,%1};" : "=l"(adup) : "f"(av[i]));
            const u64* wrow = cw + (jj*4 + i) * 8;
#pragma unroll
            for (int p = 0; p < 8; p++)
                asm("fma.rn.f32x2 %0,%1,%2,%0;" : "+l"(A[p]) : "l"(wrow[p]), "l"(adup));
        }
    }
    u64* po = (u64*)(g_p + (size_t)n * HID);
#pragma unroll
    for (int p = 0; p < 8; p += 2)
        *(ulonglong2*)(po + p) = make_ulonglong2(A[p], A[p+1]);
}

// ---- epilogue: acc pairs -> msg -> RED ----
__device__ __forceinline__ void mlp_tail_and_red(u64* A, bool v, int g, int lane) {
    if (v) {
        float m = c_par.b2;
#pragma unroll
        for (int p = 0; p < 8; p++) {
            float lo, hi;
            asm("mov.b64 {%0,%1},%2;" : "=f"(lo), "=f"(hi) : "l"(A[p]));
            m = fmaf(c_par.W2[2*p],   fmaxf(lo, 0.0f), m);
            m = fmaf(c_par.W2[2*p+1], fmaxf(hi, 0.0f), m);
        }
        atomicAdd(&g_bins[g * NSLOT + lane], m);
    }
}

// ================= TMA edge kernel (R16 + reg cap + deferred g-gather) =================
// floats: attr[8192] p[5120] mbar[4]
#define SM_ATTR 0
#define SM_P    8192
#define SM_MBAR (SM_P + TILE * PSTR)        // 13312 (8B aligned: *4 = 53248)
#define EDGE_SMEM_TMA ((SM_MBAR + 4) * 4)

__global__ void __launch_bounds__(THREADS, 4) edge_kernel_tma(
    const __grid_constant__ CUtensorMap tmap,
    const int* __restrict__ ei,
    const int* __restrict__ batch,
    int n_edges) {
    extern __shared__ __align__(1024) float sm[];
    float* sAttr = sm + SM_ATTR;
    float* sP    = sm + SM_P;
    uint32_t mbar;
    {
        uint32_t base;
        asm("{ .reg .u64 u; cvta.to.shared.u64 u, %1; cvt.u32.u64 %0, u; }"
            : "=r"(base) : "l"(sm));
        mbar = base + SM_MBAR * 4;
    }

    const int t    = threadIdx.x;
    const int lane = t & 31;
    const int e0   = blockIdx.x * TILE;
    const int e    = e0 + t;
    const bool v   = e < n_edges;

    // t0 issues the TMA immediately — nothing gates it
    if (t == 0) {
        asm volatile("mbarrier.init.shared.b64 [%0], %1;" :: "r"(mbar), "r"(1) : "memory");
        asm volatile("fence.proxy.async.shared::cta;" ::: "memory");
        asm volatile("mbarrier.arrive.expect_tx.shared.b64 _, [%0], %1;"
                     :: "r"(mbar), "r"(TILE * D_EDGE * 4) : "memory");
        uint32_t dst;
        asm("{ .reg .u64 u; cvta.to.shared.u64 u, %1; cvt.u32.u64 %0, u; }"
            : "=r"(dst) : "l"(sAttr));
        asm volatile(
            "cp.async.bulk.tensor.2d.shared::cta.global.tile.mbarrier::complete_tx::bytes "
            "[%0], [%1, {%2, %3}], [%4];"
            :: "r"(dst), "l"(&tmap), "r"(0), "r"(e0), "r"(mbar) : "memory");
    }

    // cooperative p gather under the TMA stream; src re-read directly from ei
    // (4 lanes per edge share one ei word -> 8 addrs/warp in 32B = 1 sector)
#pragma unroll
    for (int r = 0; r < (TILE * 4) / THREADS; r++) {
        int idx = r * THREADS + t;
        int el  = idx >> 2;
        int q   = idx & 3;
        int ee  = e0 + el;
        int s   = (ee < n_edges) ? __ldg(ei + ee) : 0;
        float4 pv = __ldg((const float4*)g_p + (size_t)s * 4 + q);
        *(float4*)(sP + el * PSTR + q * 4) = pv;
    }
    __syncthreads();   // sP visible; mbar init visible to all waiters

    // wait for TMA (parity 0, single use)
    asm volatile(
        "{\n\t.reg .pred P1;\n"
        "W%=:\n\tmbarrier.try_wait.parity.acquire.cta.shared::cta.b64 P1, [%0], %1, 0x989680;\n"
        "\t@P1 bra.uni D%=;\n\tbra.uni W%=;\nD%=:\n\t}"
        :: "r"(mbar), "r"(0) : "memory");

    // epilogue bin index: issued here so its ~600cy gather latency hides under compute
    int g = 0;
    if (v) g = __ldg(batch + __ldg(ei + n_edges + e));

    const float* myP = sP + t * PSTR;
    const float* myA = sAttr + t * D_EDGE;     // swizzled row
    const int swz = (t & 7);
    const u64* cw = (const u64*)&c_par.W[0][0];
    const u64* cb = (const u64*)&c_par.B[0];

    u64 A[8];
#pragma unroll
    for (int q = 0; q < 2; q++) {
        ulonglong2 p0 = *(const ulonglong2*)(myP + q * 8);
        ulonglong2 p1 = *(const ulonglong2*)(myP + q * 8 + 4);
        A[q*4+0] = add2(p0.x, cb[q*4+0]);
        A[q*4+1] = add2(p0.y, cb[q*4+1]);
        A[q*4+2] = add2(p1.x, cb[q*4+2]);
        A[q*4+3] = add2(p1.y, cb[q*4+3]);
    }
#pragma unroll
    for (int c = 0; c < 8; c++) {
        float4 a4 = *(const float4*)(myA + (c ^ swz) * 4);   // de-swizzle
        float av[4] = {a4.x, a4.y, a4.z, a4.w};
#pragma unroll
        for (int jj = 0; jj < 4; jj++) {
            u64 adup;
            asm("mov.b64 %0,{%1,%1};" : "=l"(adup) : "f"(av[jj]));
            const u64* wrow = cw + (c*4 + jj) * 8;           // uniform address, 64-bit LDCU
#pragma unroll
            for (int p = 0; p < 8; p++)
                asm("fma.rn.f32x2 %0,%1,%2,%0;" : "+l"(A[p]) : "l"(wrow[p]), "l"(adup));
        }
    }
    mlp_tail_and_red(A, v, g, lane);
}

// ================= fallback edge kernel (R9 path) =================
__global__ void __launch_bounds__(THREADS) edge_kernel_fb(
    const float* __restrict__ edge_attr,
    const int* __restrict__ ei,
    const int* __restrict__ batch,
    int n_edges) {
    extern __shared__ float smf[];
    float* sRow = smf;
    int*   sSrc = (int*)(smf + TILE * RSTRIDE);

    const int t    = threadIdx.x;
    const int lane = t & 31;
    const int e0   = blockIdx.x * TILE;
    const int e    = e0 + t;
    const bool v   = e < n_edges;

    int src = 0, g = 0;
    if (v) {
        src = __ldg(ei + e);
        g   = __ldg(batch + __ldg(ei + n_edges + e));
    }
    sSrc[t] = src;
    __syncthreads();
    {
#pragma unroll
        for (int r = 0; r < (TILE * 4) / THREADS; r++) {
            int idx = r * THREADS + t;
            int el  = idx >> 2;
            int q   = idx & 3;
            int s   = sSrc[el];
            float4 pv = __ldg((const float4*)g_p + (size_t)s * 4 + q);
            *(float4*)(sRow + el * RSTRIDE + D_EDGE + q * 4) = pv;
        }
        const float4* ga = (const float4*)edge_attr;
        const long long base  = (long long)e0 * (D_EDGE / 4);
        const long long total = (long long)n_edges * (D_EDGE / 4);
#pragma unroll
        for (int r = 0; r < (TILE * (D_EDGE / 4)) / THREADS; r++) {
            int idx = r * THREADS + t;
            float4 w = make_float4(0.f, 0.f, 0.f, 0.f);
            if (base + idx < total) w = __ldg(ga + base + idx);
            *(float4*)(sRow + (idx >> 3) * RSTRIDE + (idx & 7) * 4) = w;
        }
    }
    __syncthreads();

    const float* myRow = sRow + t * RSTRIDE;
    const u64* cw = (const u64*)&c_par.W[0][0];
    const u64* cb = (const u64*)&c_par.B[0];
    u64 A[8];
#pragma unroll
    for (int q = 0; q < 2; q++) {
        ulonglong2 p0 = *(const ulonglong2*)(myRow + D_EDGE + q * 8);
        ulonglong2 p1 = *(const ulonglong2*)(myRow + D_EDGE + q * 8 + 4);
        A[q*4+0] = add2(p0.x, cb[q*4+0]);
        A[q*4+1] = add2(p0.y, cb[q*4+1]);
        A[q*4+2] = add2(p1.x, cb[q*4+2]);
        A[q*4+3] = add2(p1.y, cb[q*4+3]);
    }
#pragma unroll
    for (int c = 0; c < 8; c++) {
        float4 a4 = *(const float4*)(myRow + c * 4);
        float av[4] = {a4.x, a4.y, a4.z, a4.w};
#pragma unroll
        for (int jj = 0; jj < 4; jj++) {
            u64 adup;
            asm("mov.b64 %0,{%1,%1};" : "=l"(adup) : "f"(av[jj]));
            const u64* wrow = cw + (c*4 + jj) * 8;
#pragma unroll
            for (int p = 0; p < 8; p++)
                asm("fma.rn.f32x2 %0,%1,%2,%0;" : "+l"(A[p]) : "l"(wrow[p]), "l"(adup));
        }
    }
    mlp_tail_and_red(A, v, g, lane);
}

// -------- finish: one block per graph, warp reduce, write + re-zero --------
__global__ void finish_kernel(float* __restrict__ out) {
    int g = blockIdx.x;
    int lane = threadIdx.x;
    float s = g_bins[g * NSLOT + lane];
    g_bins[g * NSLOT + lane] = 0.0f;
#pragma unroll
    for (int m = 16; m >= 1; m >>= 1) s += __shfl_xor_sync(0xffffffffu, s, m);
    if (lane == 0) out[g] = s;
}

#define EDGE_SMEM_FB (TILE * RSTRIDE * 4 + TILE * 4)

typedef CUresult (*EncodeFn)(CUtensorMap*, CUtensorMapDataType, cuuint32_t, void*,
                             const cuuint64_t*, const cuuint64_t*, const cuuint32_t*,
                             const cuuint32_t*, CUtensorMapInterleave, CUtensorMapSwizzle,
                             CUtensorMapL2promotion, CUtensorMapFloatOOBfill);

extern "C" void kernel_launch(void* const* d_in, const int* in_sizes, int n_in,
                              void* d_out, int out_size) {
    const float* x         = (const float*)d_in[0];
    const float* edge_attr = (const float*)d_in[1];
    const int*   ei        = (const int*)d_in[2];
    const int*   batch     = (const int*)d_in[3];
    const float* W1        = (const float*)d_in[4];
    const float* b1        = (const float*)d_in[5];
    const float* gamma     = (const float*)d_in[6];
    const float* beta      = (const float*)d_in[7];
    const float* rm        = (const float*)d_in[8];
    const float* rv        = (const float*)d_in[9];
    const float* W2        = (const float*)d_in[10];
    const float* b2        = (const float*)d_in[11];
    float* out = (float*)d_out;

    const int n_nodes = in_sizes[0] / D_NODE;
    const int n_edges = in_sizes[1] / D_EDGE;
    const int n_tiles = (n_edges + TILE - 1) / TILE;

    cudaFuncSetAttribute(edge_kernel_tma, cudaFuncAttributeMaxDynamicSharedMemorySize, EDGE_SMEM_TMA);
    cudaFuncSetAttribute(edge_kernel_fb,  cudaFuncAttributeMaxDynamicSharedMemorySize, EDGE_SMEM_FB);

    // build tensormap via runtime-resolved driver entry point (no -lcuda)
    bool use_tma = false;
    CUtensorMap tmap;
    {
        void* sym = nullptr;
        cudaDriverEntryPointQueryResult qr;
        if (cudaGetDriverEntryPoint("cuTensorMapEncodeTiled", &sym,
                                    cudaEnableDefault, &qr) == cudaSuccess &&
            qr == cudaDriverEntryPointSuccess && sym) {
            EncodeFn enc = (EncodeFn)sym;
            cuuint64_t dims[2]    = {(cuuint64_t)D_EDGE, (cuuint64_t)n_edges};
            cuuint64_t strides[1] = {(cuuint64_t)D_EDGE * sizeof(float)};
            cuuint32_t box[2]     = {(cuuint32_t)D_EDGE, (cuuint32_t)TILE};
            cuuint32_t estr[2]    = {1, 1};
            CUresult r = enc(&tmap, CU_TENSOR_MAP_DATA_TYPE_FLOAT32, 2,
                             (void*)edge_attr, dims, strides, box, estr,
                             CU_TENSOR_MAP_INTERLEAVE_NONE, CU_TENSOR_MAP_SWIZZLE_128B,
                             CU_TENSOR_MAP_L2_PROMOTION_L2_128B,
                             CU_TENSOR_MAP_FLOAT_OOB_FILL_NONE);
            use_tma = (r == CUDA_SUCCESS);
        }
    }

    void *c_addr = nullptr, *g_addr = nullptr;
    cudaGetSymbolAddress(&c_addr, c_par);
    cudaGetSymbolAddress(&g_addr, g_par);

    prep_kernel<<<8, 256>>>(W1, b1, gamma, beta, rm, rv, W2, b2);
    cudaMemcpyAsync(c_addr, g_addr, sizeof(CP), cudaMemcpyDeviceToDevice, 0);
    node_kernel<<<(n_nodes + NT - 1) / NT, NT>>>(x, n_nodes);
    if (use_tma)
        edge_kernel_tma<<<n_tiles, THREADS, EDGE_SMEM_TMA>>>(tmap, ei, batch, n_edges);
    else
        edge_kernel_fb<<<n_tiles, THREADS, EDGE_SMEM_FB>>>(edge_attr, ei, batch, n_edges);
    finish_kernel<<<N_GRAPHS_C, NSLOT>>>(out);
}